// round 1
// baseline (speedup 1.0000x reference)
#include <cuda_runtime.h>
#include <math.h>

// Problem shape (fixed by the reference)
#define BB 8
#define SS 2048
#define DD 1024

// Scratch (allocation-free rule: __device__ globals)
__device__ float g_Q[(size_t)BB * SS * DD];
__device__ float g_K[(size_t)BB * SS * DD];
__device__ float g_V[(size_t)BB * SS * DD];
__device__ float g_P[(size_t)BB * SS * SS];

// ---------------- SGEMM tile config ----------------
constexpr int BM = 128, BN = 128, BK = 16, TM = 8, TN = 8;
constexpr int NTH = (BM / TM) * (BN / TN);  // 256 threads

// C[M,N] = alpha * A[M,K] @ op(B) (+ bias), all row-major.
// TRANSB=false: B is [K,N]. TRANSB=true: B is [N,K] (C = A @ B^T).
// All dims assumed multiples of tile sizes (true for this problem).
template <bool TRANSB, bool BIAS>
__device__ __forceinline__ void sgemm_tile(const float* __restrict__ A,
                                           const float* __restrict__ Bm,
                                           float* __restrict__ C,
                                           int M, int N, int K, float alpha,
                                           const float* __restrict__ bias) {
    __shared__ float As[BK][BM];
    __shared__ float Bs[BK][BN + 4];   // +4 floats pad: row stride 528B (16B-aligned)

    const int tid = threadIdx.x;
    const int bm = blockIdx.y * BM;
    const int bn = blockIdx.x * BN;

    // A-style loader mapping (also used for transposed B): 4 threads per row, float4 each
    const int aRow = tid >> 2;          // 0..63
    const int aCol = (tid & 3) * 4;     // 0,4,8,12

    // NN B loader mapping: 32 threads per k-row, float4 each
    const int bRow = tid >> 5;          // 0..7
    const int bCol = (tid & 31) * 4;    // 0..124

    const int tRow = (tid >> 4) * TM;
    const int tCol = (tid & 15) * TN;

    float acc[TM][TN];
#pragma unroll
    for (int i = 0; i < TM; i++)
#pragma unroll
        for (int j = 0; j < TN; j++) acc[i][j] = 0.0f;

    for (int k0 = 0; k0 < K; k0 += BK) {
        // --- load A tile (transposed into As[k][m]) ---
#pragma unroll
        for (int p = 0; p < 2; p++) {
            const int r = aRow + p * 64;
            float4 v = *reinterpret_cast<const float4*>(
                A + (size_t)(bm + r) * K + k0 + aCol);
            As[aCol + 0][r] = v.x;
            As[aCol + 1][r] = v.y;
            As[aCol + 2][r] = v.z;
            As[aCol + 3][r] = v.w;
        }
        // --- load B tile ---
        if (TRANSB) {
#pragma unroll
            for (int p = 0; p < 2; p++) {
                const int r = aRow + p * 64;  // r indexes N dimension of B[N,K]
                float4 v = *reinterpret_cast<const float4*>(
                    Bm + (size_t)(bn + r) * K + k0 + aCol);
                Bs[aCol + 0][r] = v.x;
                Bs[aCol + 1][r] = v.y;
                Bs[aCol + 2][r] = v.z;
                Bs[aCol + 3][r] = v.w;
            }
        } else {
#pragma unroll
            for (int p = 0; p < 2; p++) {
                const int kk = bRow + p * 8;
                float4 v = *reinterpret_cast<const float4*>(
                    Bm + (size_t)(k0 + kk) * N + bn + bCol);
                *reinterpret_cast<float4*>(&Bs[kk][bCol]) = v;
            }
        }
        __syncthreads();

        // --- compute ---
#pragma unroll
        for (int kk = 0; kk < BK; kk++) {
            float ra[TM], rb[TN];
#pragma unroll
            for (int i = 0; i < TM; i++) ra[i] = As[kk][tRow + i];
#pragma unroll
            for (int j = 0; j < TN; j++) rb[j] = Bs[kk][tCol + j];
#pragma unroll
            for (int i = 0; i < TM; i++)
#pragma unroll
                for (int j = 0; j < TN; j++) acc[i][j] = fmaf(ra[i], rb[j], acc[i][j]);
        }
        __syncthreads();
    }

    // --- epilogue ---
#pragma unroll
    for (int i = 0; i < TM; i++) {
#pragma unroll
        for (int j = 0; j < TN; j += 4) {
            float4 v;
            v.x = acc[i][j + 0] * alpha;
            v.y = acc[i][j + 1] * alpha;
            v.z = acc[i][j + 2] * alpha;
            v.w = acc[i][j + 3] * alpha;
            if (BIAS) {
                v.x += bias[bn + tCol + j + 0];
                v.y += bias[bn + tCol + j + 1];
                v.z += bias[bn + tCol + j + 2];
                v.w += bias[bn + tCol + j + 3];
            }
            *reinterpret_cast<float4*>(
                C + (size_t)(bm + tRow + i) * N + bn + tCol + j) = v;
        }
    }
}

// ---------------- kernels ----------------

// QKV projections: z=0 -> Q, z=1 -> K, z=2 -> V
__global__ __launch_bounds__(NTH) void qkv_kernel(
    const float* __restrict__ x,
    const float* __restrict__ Wq, const float* __restrict__ bq,
    const float* __restrict__ Wk, const float* __restrict__ bk,
    const float* __restrict__ Wv, const float* __restrict__ bv) {
    const float* W;
    const float* b;
    float* out;
    if (blockIdx.z == 0) { W = Wq; b = bq; out = g_Q; }
    else if (blockIdx.z == 1) { W = Wk; b = bk; out = g_K; }
    else { W = Wv; b = bv; out = g_V; }
    sgemm_tile<false, true>(x, W, out, BB * SS, DD, DD, 1.0f, b);
}

// scores: P[b] = (Q[b] @ K[b]^T) * (1/sqrt(D))
__global__ __launch_bounds__(NTH) void scores_kernel() {
    const size_t bo = (size_t)blockIdx.z * SS * DD;
    const size_t po = (size_t)blockIdx.z * SS * SS;
    sgemm_tile<true, false>(g_Q + bo, g_K + bo, g_P + po, SS, SS, DD,
                            0.03125f /* 1/sqrt(1024) */, nullptr);
}

// softmax over each row of P (row length SS=2048), in place
__global__ __launch_bounds__(256) void softmax_kernel() {
    float* row = g_P + (size_t)blockIdx.x * SS;
    const int tid = threadIdx.x;
    const int lane = tid & 31;
    const int wid = tid >> 5;
    __shared__ float red[8];

    float v[8];
    float m = -1e30f;
#pragma unroll
    for (int i = 0; i < 8; i++) {
        v[i] = row[tid + i * 256];
        m = fmaxf(m, v[i]);
    }
#pragma unroll
    for (int o = 16; o > 0; o >>= 1)
        m = fmaxf(m, __shfl_xor_sync(0xffffffffu, m, o));
    if (lane == 0) red[wid] = m;
    __syncthreads();
    m = red[0];
#pragma unroll
    for (int w = 1; w < 8; w++) m = fmaxf(m, red[w]);
    __syncthreads();

    float s = 0.0f;
#pragma unroll
    for (int i = 0; i < 8; i++) {
        v[i] = expf(v[i] - m);
        s += v[i];
    }
#pragma unroll
    for (int o = 16; o > 0; o >>= 1) s += __shfl_xor_sync(0xffffffffu, s, o);
    if (lane == 0) red[wid] = s;
    __syncthreads();
    s = red[0];
#pragma unroll
    for (int w = 1; w < 8; w++) s += red[w];
    const float inv = 1.0f / s;
#pragma unroll
    for (int i = 0; i < 8; i++) row[tid + i * 256] = v[i] * inv;
}

// out[b] = P[b] @ V[b]
__global__ __launch_bounds__(NTH) void pv_kernel(float* __restrict__ out) {
    const size_t po = (size_t)blockIdx.z * SS * SS;
    const size_t vo = (size_t)blockIdx.z * SS * DD;
    sgemm_tile<false, false>(g_P + po, g_V + vo, out + vo, SS, DD, SS, 1.0f,
                             nullptr);
}

// ---------------- launch ----------------
extern "C" void kernel_launch(void* const* d_in, const int* in_sizes, int n_in,
                              void* d_out, int out_size) {
    const float* x  = (const float*)d_in[0];
    const float* Wq = (const float*)d_in[1];
    const float* bq = (const float*)d_in[2];
    const float* Wk = (const float*)d_in[3];
    const float* bk = (const float*)d_in[4];
    const float* Wv = (const float*)d_in[5];
    const float* bv = (const float*)d_in[6];
    float* out = (float*)d_out;

    dim3 blk(NTH);
    qkv_kernel<<<dim3(DD / BN, (BB * SS) / BM, 3), blk>>>(x, Wq, bq, Wk, bk,
                                                          Wv, bv);
    scores_kernel<<<dim3(SS / BN, SS / BM, BB), blk>>>();
    softmax_kernel<<<BB * SS, 256>>>();
    pv_kernel<<<dim3(DD / BN, SS / BM, BB), blk>>>(out);
}

// round 2
// speedup vs baseline: 2.6722x; 2.6722x over previous
#include <cuda_runtime.h>
#include <cuda_fp16.h>
#include <math.h>
#include <stdint.h>

// Problem shape (fixed by the reference)
#define BB 8
#define SS 2048
#define DD 1024

// Scratch (allocation-free rule: __device__ globals)
__device__ float g_Q[(size_t)BB * SS * DD];
__device__ float g_K[(size_t)BB * SS * DD];
__device__ float g_V[(size_t)BB * SS * DD];
__device__ float g_P[(size_t)BB * SS * SS];

// ---------------- mma / ldmatrix helpers ----------------
__device__ __forceinline__ uint32_t smem_u32(const void* p) {
    return (uint32_t)__cvta_generic_to_shared(p);
}

__device__ __forceinline__ void ldsm_x4(uint32_t& r0, uint32_t& r1,
                                        uint32_t& r2, uint32_t& r3,
                                        uint32_t addr) {
    asm volatile(
        "ldmatrix.sync.aligned.m8n8.x4.shared.b16 {%0,%1,%2,%3}, [%4];\n"
        : "=r"(r0), "=r"(r1), "=r"(r2), "=r"(r3)
        : "r"(addr));
}

__device__ __forceinline__ void ldsm_x4_t(uint32_t& r0, uint32_t& r1,
                                          uint32_t& r2, uint32_t& r3,
                                          uint32_t addr) {
    asm volatile(
        "ldmatrix.sync.aligned.m8n8.x4.trans.shared.b16 {%0,%1,%2,%3}, [%4];\n"
        : "=r"(r0), "=r"(r1), "=r"(r2), "=r"(r3)
        : "r"(addr));
}

__device__ __forceinline__ void mma16816(float* c, const uint32_t* a,
                                         uint32_t b0, uint32_t b1) {
    asm volatile(
        "mma.sync.aligned.m16n8k16.row.col.f32.f16.f16.f32 "
        "{%0,%1,%2,%3}, {%4,%5,%6,%7}, {%8,%9}, {%0,%1,%2,%3};\n"
        : "+f"(c[0]), "+f"(c[1]), "+f"(c[2]), "+f"(c[3])
        : "r"(a[0]), "r"(a[1]), "r"(a[2]), "r"(a[3]), "r"(b0), "r"(b1));
}

// 2-term fp16 split: v ~= hi + lo, rep error ~2^-22
__device__ __forceinline__ void split2(float v, __half& hi, __half& lo) {
    hi = __float2half_rn(v);
    lo = __float2half_rn(v - __half2float(hi));
}

// ---------------- HGEMM (split-fp16, fp32 I/O) ----------------
// C[M,N] = alpha * A[M,K] @ op(B) (+ bias), all row-major fp32 in gmem.
// TRANSB=false: B is [K,N]. TRANSB=true: B is [N,K] (C = A @ B^T).
// All dims multiples of tile sizes (true here).
constexpr int BM = 128, BN = 128, BK = 32;
constexpr int NTH = 256;
constexpr int ASTR = BK + 8;  // half stride, 16B-aligned rows
constexpr int BSTR = BN + 8;

template <bool TRANSB, bool BIAS>
__device__ __forceinline__ void hgemm_tile(const float* __restrict__ A,
                                           const float* __restrict__ Bm,
                                           float* __restrict__ C,
                                           int M, int N, int K, float alpha,
                                           const float* __restrict__ bias) {
    __shared__ __align__(16) __half As_hi[BM * ASTR];
    __shared__ __align__(16) __half As_lo[BM * ASTR];
    __shared__ __align__(16) __half Bs_hi[BK * BSTR];
    __shared__ __align__(16) __half Bs_lo[BK * BSTR];

    const int tid = threadIdx.x;
    const int lane = tid & 31;
    const int warp = tid >> 5;
    const int wm = warp >> 1;  // 0..3 -> 32 rows each
    const int wn = warp & 1;   // 0..1 -> 64 cols each
    const int bm = blockIdx.y * BM;
    const int bn = blockIdx.x * BN;

    float acc[2][8][4];
#pragma unroll
    for (int i = 0; i < 2; i++)
#pragma unroll
        for (int j = 0; j < 8; j++)
#pragma unroll
            for (int q = 0; q < 4; q++) acc[i][j][q] = 0.0f;

    for (int k0 = 0; k0 < K; k0 += BK) {
        // ---- load + split A tile: 128 rows x 32 k ----
        {
            const int r = tid >> 3;          // 0..31
            const int c = (tid & 7) * 4;     // 0..28
#pragma unroll
            for (int p = 0; p < 4; p++) {
                const int row = r + p * 32;
                float4 v = *reinterpret_cast<const float4*>(
                    A + (size_t)(bm + row) * K + k0 + c);
                __half h, l;
                split2(v.x, h, l); As_hi[row * ASTR + c + 0] = h; As_lo[row * ASTR + c + 0] = l;
                split2(v.y, h, l); As_hi[row * ASTR + c + 1] = h; As_lo[row * ASTR + c + 1] = l;
                split2(v.z, h, l); As_hi[row * ASTR + c + 2] = h; As_lo[row * ASTR + c + 2] = l;
                split2(v.w, h, l); As_hi[row * ASTR + c + 3] = h; As_lo[row * ASTR + c + 3] = l;
            }
        }
        // ---- load + split B tile into Bs[k][n] ----
        if (TRANSB) {
            const int n = tid >> 3;          // 0..31
            const int c = (tid & 7) * 4;     // k offset
#pragma unroll
            for (int p = 0; p < 4; p++) {
                const int nn = n + p * 32;
                float4 v = *reinterpret_cast<const float4*>(
                    Bm + (size_t)(bn + nn) * K + k0 + c);
                __half h, l;
                split2(v.x, h, l); Bs_hi[(c + 0) * BSTR + nn] = h; Bs_lo[(c + 0) * BSTR + nn] = l;
                split2(v.y, h, l); Bs_hi[(c + 1) * BSTR + nn] = h; Bs_lo[(c + 1) * BSTR + nn] = l;
                split2(v.z, h, l); Bs_hi[(c + 2) * BSTR + nn] = h; Bs_lo[(c + 2) * BSTR + nn] = l;
                split2(v.w, h, l); Bs_hi[(c + 3) * BSTR + nn] = h; Bs_lo[(c + 3) * BSTR + nn] = l;
            }
        } else {
            const int r = tid >> 5;          // 0..7
            const int c = (tid & 31) * 4;    // 0..124
#pragma unroll
            for (int p = 0; p < 4; p++) {
                const int kk = r + p * 8;
                float4 v = *reinterpret_cast<const float4*>(
                    Bm + (size_t)(k0 + kk) * N + bn + c);
                __half h, l;
                split2(v.x, h, l); Bs_hi[kk * BSTR + c + 0] = h; Bs_lo[kk * BSTR + c + 0] = l;
                split2(v.y, h, l); Bs_hi[kk * BSTR + c + 1] = h; Bs_lo[kk * BSTR + c + 1] = l;
                split2(v.z, h, l); Bs_hi[kk * BSTR + c + 2] = h; Bs_lo[kk * BSTR + c + 2] = l;
                split2(v.w, h, l); Bs_hi[kk * BSTR + c + 3] = h; Bs_lo[kk * BSTR + c + 3] = l;
            }
        }
        __syncthreads();

        // ---- compute: two k16 sub-steps ----
#pragma unroll
        for (int kf = 0; kf < 2; kf++) {
            uint32_t ah[2][4], al[2][4];
#pragma unroll
            for (int mf = 0; mf < 2; mf++) {
                const int row = wm * 32 + mf * 16 + (lane & 15);
                const int col = kf * 16 + (lane >> 4) * 8;
                ldsm_x4(ah[mf][0], ah[mf][1], ah[mf][2], ah[mf][3],
                        smem_u32(&As_hi[row * ASTR + col]));
                ldsm_x4(al[mf][0], al[mf][1], al[mf][2], al[mf][3],
                        smem_u32(&As_lo[row * ASTR + col]));
            }
#pragma unroll
            for (int nq = 0; nq < 4; nq++) {  // 16 n-cols per iteration
                const int krow = kf * 16 + (lane & 15);
                const int ncol = wn * 64 + nq * 16 + (lane >> 4) * 8;
                uint32_t bh[4], bl[4];
                ldsm_x4_t(bh[0], bh[1], bh[2], bh[3],
                          smem_u32(&Bs_hi[krow * BSTR + ncol]));
                ldsm_x4_t(bl[0], bl[1], bl[2], bl[3],
                          smem_u32(&Bs_lo[krow * BSTR + ncol]));
#pragma unroll
                for (int h = 0; h < 2; h++) {
                    const int nf = nq * 2 + h;
#pragma unroll
                    for (int mf = 0; mf < 2; mf++) {
                        float* c = acc[mf][nf];
                        mma16816(c, ah[mf], bh[h * 2], bh[h * 2 + 1]);  // hi*hi
                        mma16816(c, ah[mf], bl[h * 2], bl[h * 2 + 1]);  // hi*lo
                        mma16816(c, al[mf], bh[h * 2], bh[h * 2 + 1]);  // lo*hi
                    }
                }
            }
        }
        __syncthreads();
    }

    // ---- epilogue ----
#pragma unroll
    for (int mf = 0; mf < 2; mf++) {
#pragma unroll
        for (int nf = 0; nf < 8; nf++) {
            const int m = bm + wm * 32 + mf * 16 + (lane >> 2);
            const int n = bn + wn * 64 + nf * 8 + (lane & 3) * 2;
            float2 v0, v1;
            v0.x = acc[mf][nf][0] * alpha;
            v0.y = acc[mf][nf][1] * alpha;
            v1.x = acc[mf][nf][2] * alpha;
            v1.y = acc[mf][nf][3] * alpha;
            if (BIAS) {
                v0.x += bias[n]; v0.y += bias[n + 1];
                v1.x += bias[n]; v1.y += bias[n + 1];
            }
            *reinterpret_cast<float2*>(C + (size_t)m * N + n) = v0;
            *reinterpret_cast<float2*>(C + (size_t)(m + 8) * N + n) = v1;
        }
    }
}

// ---------------- kernels ----------------

__global__ __launch_bounds__(NTH, 2) void qkv_kernel(
    const float* __restrict__ x,
    const float* __restrict__ Wq, const float* __restrict__ bq,
    const float* __restrict__ Wk, const float* __restrict__ bk,
    const float* __restrict__ Wv, const float* __restrict__ bv) {
    const float* W;
    const float* b;
    float* out;
    if (blockIdx.z == 0) { W = Wq; b = bq; out = g_Q; }
    else if (blockIdx.z == 1) { W = Wk; b = bk; out = g_K; }
    else { W = Wv; b = bv; out = g_V; }
    hgemm_tile<false, true>(x, W, out, BB * SS, DD, DD, 1.0f, b);
}

// scores: P[b] = (Q[b] @ K[b]^T) * (1/sqrt(D))
__global__ __launch_bounds__(NTH, 2) void scores_kernel() {
    const size_t bo = (size_t)blockIdx.z * SS * DD;
    const size_t po = (size_t)blockIdx.z * SS * SS;
    hgemm_tile<true, false>(g_Q + bo, g_K + bo, g_P + po, SS, SS, DD,
                            0.03125f /* 1/sqrt(1024) */, nullptr);
}

// softmax over each row of P (row length SS=2048), in place
__global__ __launch_bounds__(256) void softmax_kernel() {
    float* row = g_P + (size_t)blockIdx.x * SS;
    const int tid = threadIdx.x;
    const int lane = tid & 31;
    const int wid = tid >> 5;
    __shared__ float red[8];

    float v[8];
    float m = -1e30f;
#pragma unroll
    for (int i = 0; i < 8; i++) {
        v[i] = row[tid + i * 256];
        m = fmaxf(m, v[i]);
    }
#pragma unroll
    for (int o = 16; o > 0; o >>= 1)
        m = fmaxf(m, __shfl_xor_sync(0xffffffffu, m, o));
    if (lane == 0) red[wid] = m;
    __syncthreads();
    m = red[0];
#pragma unroll
    for (int w = 1; w < 8; w++) m = fmaxf(m, red[w]);
    __syncthreads();

    float s = 0.0f;
#pragma unroll
    for (int i = 0; i < 8; i++) {
        v[i] = expf(v[i] - m);
        s += v[i];
    }
#pragma unroll
    for (int o = 16; o > 0; o >>= 1) s += __shfl_xor_sync(0xffffffffu, s, o);
    if (lane == 0) red[wid] = s;
    __syncthreads();
    s = red[0];
#pragma unroll
    for (int w = 1; w < 8; w++) s += red[w];
    const float inv = 1.0f / s;
#pragma unroll
    for (int i = 0; i < 8; i++) row[tid + i * 256] = v[i] * inv;
}

// out[b] = P[b] @ V[b]
__global__ __launch_bounds__(NTH, 2) void pv_kernel(float* __restrict__ out) {
    const size_t po = (size_t)blockIdx.z * SS * SS;
    const size_t vo = (size_t)blockIdx.z * SS * DD;
    hgemm_tile<false, false>(g_P + po, g_V + vo, out + vo, SS, DD, SS, 1.0f,
                             nullptr);
}

// ---------------- launch ----------------
extern "C" void kernel_launch(void* const* d_in, const int* in_sizes, int n_in,
                              void* d_out, int out_size) {
    const float* x  = (const float*)d_in[0];
    const float* Wq = (const float*)d_in[1];
    const float* bq = (const float*)d_in[2];
    const float* Wk = (const float*)d_in[3];
    const float* bk = (const float*)d_in[4];
    const float* Wv = (const float*)d_in[5];
    const float* bv = (const float*)d_in[6];
    float* out = (float*)d_out;

    dim3 blk(NTH);
    qkv_kernel<<<dim3(DD / BN, (BB * SS) / BM, 3), blk>>>(x, Wq, bq, Wk, bk,
                                                          Wv, bv);
    scores_kernel<<<dim3(SS / BN, SS / BM, BB), blk>>>();
    softmax_kernel<<<BB * SS, 256>>>();
    pv_kernel<<<dim3(DD / BN, SS / BM, BB), blk>>>(out);
}

// round 4
// speedup vs baseline: 3.0699x; 1.1488x over previous
#include <cuda_runtime.h>
#include <cuda_fp16.h>
#include <math.h>
#include <stdint.h>

// Problem shape (fixed by the reference)
#define BB 8
#define SS 2048
#define DD 1024

constexpr size_t BSD = (size_t)BB * SS * DD;   // 16M elems

// ---------------- device scratch (allocation-free rule) ----------------
__device__ __half gx_hi[BSD], gx_lo[BSD];
__device__ __half gw_hi[3ull * DD * DD], gw_lo[3ull * DD * DD];
__device__ __half gqkv_hi[3ull * BB * SS * DD], gqkv_lo[3ull * BB * SS * DD];
__device__ __half gkT_hi[BSD], gkT_lo[BSD];
__device__ float g_P[(size_t)BB * SS * SS];
__device__ __half g_Ph[(size_t)BB * SS * SS];

// ---------------- PTX helpers ----------------
__device__ __forceinline__ uint32_t smem_u32(const void* p) {
    return (uint32_t)__cvta_generic_to_shared(p);
}

__device__ __forceinline__ void ldsm_x4(uint32_t& r0, uint32_t& r1,
                                        uint32_t& r2, uint32_t& r3,
                                        uint32_t addr) {
    asm volatile(
        "ldmatrix.sync.aligned.m8n8.x4.shared.b16 {%0,%1,%2,%3}, [%4];\n"
        : "=r"(r0), "=r"(r1), "=r"(r2), "=r"(r3)
        : "r"(addr));
}

__device__ __forceinline__ void ldsm_x4_t(uint32_t& r0, uint32_t& r1,
                                          uint32_t& r2, uint32_t& r3,
                                          uint32_t addr) {
    asm volatile(
        "ldmatrix.sync.aligned.m8n8.x4.trans.shared.b16 {%0,%1,%2,%3}, [%4];\n"
        : "=r"(r0), "=r"(r1), "=r"(r2), "=r"(r3)
        : "r"(addr));
}

__device__ __forceinline__ void mma16816(float* c, const uint32_t* a,
                                         uint32_t b0, uint32_t b1) {
    asm volatile(
        "mma.sync.aligned.m16n8k16.row.col.f32.f16.f16.f32 "
        "{%0,%1,%2,%3}, {%4,%5,%6,%7}, {%8,%9}, {%0,%1,%2,%3};\n"
        : "+f"(c[0]), "+f"(c[1]), "+f"(c[2]), "+f"(c[3])
        : "r"(a[0]), "r"(a[1]), "r"(a[2]), "r"(a[3]), "r"(b0), "r"(b1));
}

__device__ __forceinline__ void cp16(uint32_t dst, const void* src) {
    asm volatile("cp.async.cg.shared.global [%0], [%1], 16;\n" ::"r"(dst),
                 "l"(src)
                 : "memory");
}
#define CP_COMMIT() asm volatile("cp.async.commit_group;\n" ::: "memory")
#define CP_WAIT1() asm volatile("cp.async.wait_group 1;\n" ::: "memory")
#define CP_WAIT0() asm volatile("cp.async.wait_group 0;\n" ::: "memory")

#define SWZ(x) ((uint32_t)(x) ^ ((((uint32_t)(x)) >> 3) & 0x70))

// ---------------- GEMM config ----------------
constexpr int BM = 128, BN = 128, BK = 64, NTH = 256, STAGES = 3;

template <bool A_LO, bool B_LO>
struct SL {
    static constexpr int AH = 0;
    static constexpr int AL = A_LO ? 16384 : 0;        // aliases AH if unused
    static constexpr int BH = 16384 + (A_LO ? 16384 : 0);
    static constexpr int BL = BH + 16384;              // valid only if B_LO
    static constexpr int BYTES = BH + 16384 + (B_LO ? 16384 : 0);
};

// C[M,N] = alpha * A[M,K] @ B[K,N] (+bias / split-out for QKV).
// A in fp16 hi(/lo) [M,K] row-major; B in fp16 hi(/lo) [K,N] row-major.
// All dims multiples of tile sizes. z = batch/projection index.
template <bool A_LO, bool B_LO, bool QKV>
__global__ void __launch_bounds__(NTH, 1) hgemm(
    const __half* __restrict__ Ah, const __half* __restrict__ Al,
    const __half* __restrict__ Bh, const __half* __restrict__ Bl,
    float* __restrict__ Cf, __half* __restrict__ Ch, __half* __restrict__ Cl,
    int N, int K, long long sA, long long sB, long long sC, float alpha,
    const float* __restrict__ b0, const float* __restrict__ b1,
    const float* __restrict__ b2) {
    using L = SL<A_LO, B_LO>;
    extern __shared__ char smem[];
    const uint32_t sb = smem_u32(smem);
    const int tid = threadIdx.x, lane = tid & 31, warp = tid >> 5;
    const int wm = warp >> 1, wn = warp & 1;
    const int z = blockIdx.z;
    const int bm = blockIdx.y * BM, bn = blockIdx.x * BN;

    const __half* Agh = Ah + (size_t)z * sA + (size_t)bm * K;
    const __half* Agl = A_LO ? (Al + (size_t)z * sA + (size_t)bm * K) : nullptr;
    const __half* Bgh = Bh + (size_t)z * sB;
    const __half* Bgl = B_LO ? (Bl + (size_t)z * sB) : nullptr;

    auto issue = [&](int s) {
        const uint32_t so = sb + (uint32_t)(s % STAGES) * L::BYTES;
        const int k0 = s * BK;
#pragma unroll
        for (int i = 0; i < 4; i++) {
            const int idx = tid + i * NTH;
            const int row = idx >> 3, c = idx & 7;
            const size_t g = (size_t)row * K + k0 + c * 8;
            const uint32_t d = SWZ(row * 128 + c * 16);
            cp16(so + L::AH + d, Agh + g);
            if (A_LO) cp16(so + L::AL + d, Agl + g);
        }
#pragma unroll
        for (int i = 0; i < 4; i++) {
            const int idx = tid + i * NTH;
            const int krow = idx >> 4, sub = (idx >> 3) & 1, c = idx & 7;
            const size_t g = (size_t)(k0 + krow) * N + bn + sub * 64 + c * 8;
            const uint32_t d = (uint32_t)sub * 8192 + SWZ(krow * 128 + c * 16);
            cp16(so + L::BH + d, Bgh + g);
            if (B_LO) cp16(so + L::BL + d, Bgl + g);
        }
        CP_COMMIT();
    };

    float acc[2][8][4];
#pragma unroll
    for (int i = 0; i < 2; i++)
#pragma unroll
        for (int j = 0; j < 8; j++)
#pragma unroll
            for (int q = 0; q < 4; q++) acc[i][j][q] = 0.0f;

    const int ns = K / BK;
    issue(0);
    issue(1);
    for (int s = 0; s < ns; s++) {
        if (s == ns - 1) { CP_WAIT0(); } else { CP_WAIT1(); }
        __syncthreads();
        const uint32_t so = sb + (uint32_t)(s % STAGES) * L::BYTES;
#pragma unroll
        for (int kf = 0; kf < 4; kf++) {
            uint32_t ah[2][4], al[2][4];
#pragma unroll
            for (int mf = 0; mf < 2; mf++) {
                const int rowA = wm * 32 + mf * 16 + (lane & 15);
                const int col2 = (kf * 16 + (lane >> 4) * 8) * 2;
                const uint32_t off = SWZ(rowA * 128 + col2);
                ldsm_x4(ah[mf][0], ah[mf][1], ah[mf][2], ah[mf][3],
                        so + L::AH + off);
                if (A_LO)
                    ldsm_x4(al[mf][0], al[mf][1], al[mf][2], al[mf][3],
                            so + L::AL + off);
            }
#pragma unroll
            for (int nq = 0; nq < 4; nq++) {
                const int krow = kf * 16 + (lane & 15);
                const int nloc2 = (nq * 16 + (lane >> 4) * 8) * 2;
                const uint32_t boff =
                    (uint32_t)wn * 8192 + SWZ(krow * 128 + nloc2);
                uint32_t bh[4], bl[4];
                ldsm_x4_t(bh[0], bh[1], bh[2], bh[3], so + L::BH + boff);
                if (B_LO)
                    ldsm_x4_t(bl[0], bl[1], bl[2], bl[3], so + L::BL + boff);
#pragma unroll
                for (int h = 0; h < 2; h++) {
                    const int nf = nq * 2 + h;
#pragma unroll
                    for (int mf = 0; mf < 2; mf++) {
                        mma16816(acc[mf][nf], ah[mf], bh[h * 2], bh[h * 2 + 1]);
                        if (B_LO)
                            mma16816(acc[mf][nf], ah[mf], bl[h * 2],
                                     bl[h * 2 + 1]);
                        if (A_LO)
                            mma16816(acc[mf][nf], al[mf], bh[h * 2],
                                     bh[h * 2 + 1]);
                    }
                }
            }
        }
        __syncthreads();
        if (s + 2 < ns) issue(s + 2);
    }

    // ---- epilogue ----
    const float* bias = nullptr;
    if (QKV) bias = (z == 0) ? b0 : (z == 1) ? b1 : b2;
#pragma unroll
    for (int mf = 0; mf < 2; mf++) {
#pragma unroll
        for (int nf = 0; nf < 8; nf++) {
            const int m = bm + wm * 32 + mf * 16 + (lane >> 2);
            const int n = bn + wn * 64 + nf * 8 + (lane & 3) * 2;
            float2 v0, v1;
            v0.x = acc[mf][nf][0] * alpha;
            v0.y = acc[mf][nf][1] * alpha;
            v1.x = acc[mf][nf][2] * alpha;
            v1.y = acc[mf][nf][3] * alpha;
            if (QKV) {
                v0.x += bias[n]; v0.y += bias[n + 1];
                v1.x += bias[n]; v1.y += bias[n + 1];
                const size_t o0 = (size_t)z * sC + (size_t)m * N + n;
                const size_t o1 = (size_t)z * sC + (size_t)(m + 8) * N + n;
                __half2 h0 = __floats2half2_rn(v0.x, v0.y);
                __half2 h1 = __floats2half2_rn(v1.x, v1.y);
                float2 f0 = __half22float2(h0);
                float2 f1 = __half22float2(h1);
                __half2 l0 = __floats2half2_rn(v0.x - f0.x, v0.y - f0.y);
                __half2 l1 = __floats2half2_rn(v1.x - f1.x, v1.y - f1.y);
                *reinterpret_cast<__half2*>(Ch + o0) = h0;
                *reinterpret_cast<__half2*>(Cl + o0) = l0;
                *reinterpret_cast<__half2*>(Ch + o1) = h1;
                *reinterpret_cast<__half2*>(Cl + o1) = l1;
            } else {
                float* c = Cf + (size_t)z * sC;
                *reinterpret_cast<float2*>(c + (size_t)m * N + n) = v0;
                *reinterpret_cast<float2*>(c + (size_t)(m + 8) * N + n) = v1;
            }
        }
    }
}

// ---------------- elementwise fp32 -> fp16 hi/lo split ----------------
__global__ void __launch_bounds__(256) split_kernel(
    const float* __restrict__ in, __half* __restrict__ hi,
    __half* __restrict__ lo, int n4) {
    const int i = blockIdx.x * 256 + threadIdx.x;
    if (i >= n4) return;
    const float4 v = reinterpret_cast<const float4*>(in)[i];
    __half2 h0 = __floats2half2_rn(v.x, v.y);
    __half2 h1 = __floats2half2_rn(v.z, v.w);
    float2 f0 = __half22float2(h0);
    float2 f1 = __half22float2(h1);
    __half2 l0 = __floats2half2_rn(v.x - f0.x, v.y - f0.y);
    __half2 l1 = __floats2half2_rn(v.z - f1.x, v.w - f1.y);
    reinterpret_cast<__half2*>(hi)[i * 2 + 0] = h0;
    reinterpret_cast<__half2*>(hi)[i * 2 + 1] = h1;
    reinterpret_cast<__half2*>(lo)[i * 2 + 0] = l0;
    reinterpret_cast<__half2*>(lo)[i * 2 + 1] = l1;
}

// ---------------- fp16 transpose, 32x32 tiles, per-batch ----------------
__global__ void __launch_bounds__(256) transposeH(
    const __half* __restrict__ in, __half* __restrict__ out, int R, int C) {
    __shared__ __half t[32][33];
    const int z = blockIdx.z;
    in += (size_t)z * R * C;
    out += (size_t)z * R * C;
    const int r0 = blockIdx.y * 32, c0 = blockIdx.x * 32;
    const int tx = threadIdx.x, ty = threadIdx.y;
#pragma unroll
    for (int i = 0; i < 4; i++)
        t[ty + i * 8][tx] = in[(size_t)(r0 + ty + i * 8) * C + c0 + tx];
    __syncthreads();
#pragma unroll
    for (int i = 0; i < 4; i++)
        out[(size_t)(c0 + ty + i * 8) * R + r0 + tx] = t[tx][ty + i * 8];
}

// ---------------- softmax: fp32 P row -> fp16 hi P row ----------------
__global__ void __launch_bounds__(256) softmax_kernel() {
    const float* row = g_P + (size_t)blockIdx.x * SS;
    __half* orow = g_Ph + (size_t)blockIdx.x * SS;
    const int tid = threadIdx.x;
    const int lane = tid & 31;
    const int wid = tid >> 5;
    __shared__ float red[8];

    float v[8];
    float m = -1e30f;
#pragma unroll
    for (int i = 0; i < 8; i++) {
        v[i] = row[tid + i * 256];
        m = fmaxf(m, v[i]);
    }
#pragma unroll
    for (int o = 16; o > 0; o >>= 1)
        m = fmaxf(m, __shfl_xor_sync(0xffffffffu, m, o));
    if (lane == 0) red[wid] = m;
    __syncthreads();
    m = red[0];
#pragma unroll
    for (int w = 1; w < 8; w++) m = fmaxf(m, red[w]);
    __syncthreads();

    float s = 0.0f;
#pragma unroll
    for (int i = 0; i < 8; i++) {
        v[i] = expf(v[i] - m);
        s += v[i];
    }
#pragma unroll
    for (int o = 16; o > 0; o >>= 1) s += __shfl_xor_sync(0xffffffffu, s, o);
    if (lane == 0) red[wid] = s;
    __syncthreads();
    s = red[0];
#pragma unroll
    for (int w = 1; w < 8; w++) s += red[w];
    const float inv = 1.0f / s;
#pragma unroll
    for (int i = 0; i < 8; i++)
        orow[tid + i * 256] = __float2half_rn(v[i] * inv);
}

// ---------------- launch ----------------
extern "C" void kernel_launch(void* const* d_in, const int* in_sizes, int n_in,
                              void* d_out, int out_size) {
    const float* x  = (const float*)d_in[0];
    const float* Wq = (const float*)d_in[1];
    const float* bq = (const float*)d_in[2];
    const float* Wk = (const float*)d_in[3];
    const float* bk = (const float*)d_in[4];
    const float* Wv = (const float*)d_in[5];
    const float* bv = (const float*)d_in[6];
    float* out = (float*)d_out;

    __half *xh, *xl, *wh, *wl, *qkvh, *qkvl, *kth, *ktl, *ph;
    float* p;
    cudaGetSymbolAddress((void**)&xh, gx_hi);
    cudaGetSymbolAddress((void**)&xl, gx_lo);
    cudaGetSymbolAddress((void**)&wh, gw_hi);
    cudaGetSymbolAddress((void**)&wl, gw_lo);
    cudaGetSymbolAddress((void**)&qkvh, gqkv_hi);
    cudaGetSymbolAddress((void**)&qkvl, gqkv_lo);
    cudaGetSymbolAddress((void**)&kth, gkT_hi);
    cudaGetSymbolAddress((void**)&ktl, gkT_lo);
    cudaGetSymbolAddress((void**)&p, g_P);
    cudaGetSymbolAddress((void**)&ph, g_Ph);

    constexpr int SM3 = SL<true, true>::BYTES * STAGES;   // 196608
    constexpr int SM2 = SL<false, true>::BYTES * STAGES;  // 147456
    cudaFuncSetAttribute(hgemm<true, true, true>,
                         cudaFuncAttributeMaxDynamicSharedMemorySize, SM3);
    cudaFuncSetAttribute(hgemm<true, true, false>,
                         cudaFuncAttributeMaxDynamicSharedMemorySize, SM3);
    cudaFuncSetAttribute(hgemm<false, true, false>,
                         cudaFuncAttributeMaxDynamicSharedMemorySize, SM2);

    // 1) split inputs to fp16 hi/lo
    split_kernel<<<(int)(BSD / 4 / 256), 256>>>(x, xh, xl, (int)(BSD / 4));
    const int wn4 = DD * DD / 4;
    split_kernel<<<wn4 / 256, 256>>>(Wq, wh + 0ull * DD * DD, wl + 0ull * DD * DD, wn4);
    split_kernel<<<wn4 / 256, 256>>>(Wk, wh + 1ull * DD * DD, wl + 1ull * DD * DD, wn4);
    split_kernel<<<wn4 / 256, 256>>>(Wv, wh + 2ull * DD * DD, wl + 2ull * DD * DD, wn4);

    // 2) QKV: C[16384,1024] = x @ W + bias (B = W natural [K=d_in, N=d_out])
    hgemm<true, true, true><<<dim3(DD / BN, (BB * SS) / BM, 3), NTH, SM3>>>(
        xh, xl, wh, wl, nullptr, qkvh, qkvl, DD, DD,
        0LL, (long long)DD * DD, (long long)BSD, 1.0f, bq, bk, bv);

    // 3) K^T per batch: [2048,1024] -> [1024,2048], hi and lo
    dim3 tb(32, 8);
    transposeH<<<dim3(DD / 32, SS / 32, BB), tb>>>(qkvh + BSD, kth, SS, DD);
    transposeH<<<dim3(DD / 32, SS / 32, BB), tb>>>(qkvl + BSD, ktl, SS, DD);

    // 4) scores: P[b] = (Q[b] @ K[b]^T) / 32   (B = K^T [K=d, N=s])
    hgemm<true, true, false><<<dim3(SS / BN, SS / BM, BB), NTH, SM3>>>(
        qkvh, qkvl, kth, ktl, p, nullptr, nullptr, SS, DD,
        (long long)SS * DD, (long long)DD * SS, (long long)SS * SS,
        0.03125f, nullptr, nullptr, nullptr);

    // 5) softmax (fp32 in, fp16-hi out)
    softmax_kernel<<<BB * SS, 256>>>();

    // 6) out[b] = P[b] @ V[b]   (A = P hi-only, B = V natural [K=s, N=d])
    hgemm<false, true, false><<<dim3(DD / BN, SS / BM, BB), NTH, SM2>>>(
        ph, nullptr, qkvh + 2 * BSD, qkvl + 2 * BSD, out, nullptr, nullptr,
        DD, SS, (long long)SS * SS, (long long)SS * DD, (long long)SS * DD,
        1.0f, nullptr, nullptr, nullptr);
}

// round 5
// speedup vs baseline: 3.3388x; 1.0876x over previous
#include <cuda_runtime.h>
#include <cuda_fp16.h>
#include <math.h>
#include <stdint.h>

// Problem shape (fixed by the reference)
#define BB 8
#define SS 2048
#define DD 1024

constexpr size_t BSD = (size_t)BB * SS * DD;   // 16M elems

// ---------------- device scratch (allocation-free rule) ----------------
__device__ __half gx_hi[BSD], gx_lo[BSD];
__device__ __half gw_hi[3ull * DD * DD], gw_lo[3ull * DD * DD];
__device__ __half gqkv_hi[3ull * BB * SS * DD], gqkv_lo[3ull * BB * SS * DD];
__device__ __half gkT_hi[BSD], gkT_lo[BSD];
__device__ float g_P[(size_t)BB * SS * SS];
__device__ __half g_Ph[(size_t)BB * SS * SS];

// ---------------- PTX helpers ----------------
__device__ __forceinline__ uint32_t smem_u32(const void* p) {
    return (uint32_t)__cvta_generic_to_shared(p);
}

__device__ __forceinline__ void ldsm_x4(uint32_t& r0, uint32_t& r1,
                                        uint32_t& r2, uint32_t& r3,
                                        uint32_t addr) {
    asm volatile(
        "ldmatrix.sync.aligned.m8n8.x4.shared.b16 {%0,%1,%2,%3}, [%4];\n"
        : "=r"(r0), "=r"(r1), "=r"(r2), "=r"(r3)
        : "r"(addr));
}

__device__ __forceinline__ void ldsm_x4_t(uint32_t& r0, uint32_t& r1,
                                          uint32_t& r2, uint32_t& r3,
                                          uint32_t addr) {
    asm volatile(
        "ldmatrix.sync.aligned.m8n8.x4.trans.shared.b16 {%0,%1,%2,%3}, [%4];\n"
        : "=r"(r0), "=r"(r1), "=r"(r2), "=r"(r3)
        : "r"(addr));
}

__device__ __forceinline__ void mma16816(float* c, const uint32_t* a,
                                         uint32_t b0, uint32_t b1) {
    asm volatile(
        "mma.sync.aligned.m16n8k16.row.col.f32.f16.f16.f32 "
        "{%0,%1,%2,%3}, {%4,%5,%6,%7}, {%8,%9}, {%0,%1,%2,%3};\n"
        : "+f"(c[0]), "+f"(c[1]), "+f"(c[2]), "+f"(c[3])
        : "r"(a[0]), "r"(a[1]), "r"(a[2]), "r"(a[3]), "r"(b0), "r"(b1));
}

__device__ __forceinline__ void cp16(uint32_t dst, const void* src) {
    asm volatile("cp.async.cg.shared.global [%0], [%1], 16;\n" ::"r"(dst),
                 "l"(src)
                 : "memory");
}
#define CP_COMMIT() asm volatile("cp.async.commit_group;\n" ::: "memory")
#define CP_WAIT1() asm volatile("cp.async.wait_group 1;\n" ::: "memory")
#define CP_WAIT0() asm volatile("cp.async.wait_group 0;\n" ::: "memory")

#define SWZ(x) ((uint32_t)(x) ^ ((((uint32_t)(x)) >> 3) & 0x70))

// ---------------- GEMM config ----------------
constexpr int BM = 128, BN = 128, BK = 64, NTH = 256, STAGES = 3;

template <bool A_LO, bool B_LO>
struct SL {
    static constexpr int AH = 0;
    static constexpr int AL = A_LO ? 16384 : 0;        // aliases AH if unused
    static constexpr int BH = 16384 + (A_LO ? 16384 : 0);
    static constexpr int BL = BH + 16384;              // valid only if B_LO
    static constexpr int BYTES = BH + 16384 + (B_LO ? 16384 : 0);
};

// C[M,N] = alpha * A[M,K] @ B[K,N] (+bias / split-out for QKV).
// A in fp16 hi(/lo) [M,K] row-major; B in fp16 hi(/lo) [K,N] row-major.
// All dims multiples of tile sizes. z = batch/projection index.
template <bool A_LO, bool B_LO, bool QKV>
__global__ void __launch_bounds__(NTH, 1) hgemm(
    const __half* __restrict__ Ah, const __half* __restrict__ Al,
    const __half* __restrict__ Bh, const __half* __restrict__ Bl,
    float* __restrict__ Cf, __half* __restrict__ Ch, __half* __restrict__ Cl,
    int N, int K, long long sA, long long sB, long long sC, float alpha,
    const float* __restrict__ b0, const float* __restrict__ b1,
    const float* __restrict__ b2) {
    using L = SL<A_LO, B_LO>;
    extern __shared__ char smem[];
    const uint32_t sb = smem_u32(smem);
    const int tid = threadIdx.x, lane = tid & 31, warp = tid >> 5;
    const int wm = warp >> 1, wn = warp & 1;
    const int z = blockIdx.z;
    const int bm = blockIdx.y * BM, bn = blockIdx.x * BN;

    const __half* Agh = Ah + (size_t)z * sA + (size_t)bm * K;
    const __half* Agl = A_LO ? (Al + (size_t)z * sA + (size_t)bm * K) : nullptr;
    const __half* Bgh = Bh + (size_t)z * sB;
    const __half* Bgl = B_LO ? (Bl + (size_t)z * sB) : nullptr;

    auto issue = [&](int s) {
        const uint32_t so = sb + (uint32_t)(s % STAGES) * L::BYTES;
        const int k0 = s * BK;
#pragma unroll
        for (int i = 0; i < 4; i++) {
            const int idx = tid + i * NTH;
            const int row = idx >> 3, c = idx & 7;
            const size_t g = (size_t)row * K + k0 + c * 8;
            const uint32_t d = SWZ(row * 128 + c * 16);
            cp16(so + L::AH + d, Agh + g);
            if (A_LO) cp16(so + L::AL + d, Agl + g);
        }
#pragma unroll
        for (int i = 0; i < 4; i++) {
            const int idx = tid + i * NTH;
            const int krow = idx >> 4, sub = (idx >> 3) & 1, c = idx & 7;
            const size_t g = (size_t)(k0 + krow) * N + bn + sub * 64 + c * 8;
            const uint32_t d = (uint32_t)sub * 8192 + SWZ(krow * 128 + c * 16);
            cp16(so + L::BH + d, Bgh + g);
            if (B_LO) cp16(so + L::BL + d, Bgl + g);
        }
        CP_COMMIT();
    };

    float acc[2][8][4];
#pragma unroll
    for (int i = 0; i < 2; i++)
#pragma unroll
        for (int j = 0; j < 8; j++)
#pragma unroll
            for (int q = 0; q < 4; q++) acc[i][j][q] = 0.0f;

    const int ns = K / BK;
    issue(0);
    issue(1);
    for (int s = 0; s < ns; s++) {
        if (s == ns - 1) { CP_WAIT0(); } else { CP_WAIT1(); }
        __syncthreads();
        if (s + 2 < ns) issue(s + 2);  // overlaps with compute below
        const uint32_t so = sb + (uint32_t)(s % STAGES) * L::BYTES;
#pragma unroll
        for (int kf = 0; kf < 4; kf++) {
            // ---- preload ALL fragments for this k16 slice ----
            uint32_t ah[2][4], al[2][4], bh[4][4], bl[4][4];
#pragma unroll
            for (int mf = 0; mf < 2; mf++) {
                const int rowA = wm * 32 + mf * 16 + (lane & 15);
                const int col2 = (kf * 16 + (lane >> 4) * 8) * 2;
                const uint32_t off = SWZ(rowA * 128 + col2);
                ldsm_x4(ah[mf][0], ah[mf][1], ah[mf][2], ah[mf][3],
                        so + L::AH + off);
                if (A_LO)
                    ldsm_x4(al[mf][0], al[mf][1], al[mf][2], al[mf][3],
                            so + L::AL + off);
            }
#pragma unroll
            for (int nq = 0; nq < 4; nq++) {
                const int krow = kf * 16 + (lane & 15);
                const int nloc2 = (nq * 16 + (lane >> 4) * 8) * 2;
                const uint32_t boff =
                    (uint32_t)wn * 8192 + SWZ(krow * 128 + nloc2);
                ldsm_x4_t(bh[nq][0], bh[nq][1], bh[nq][2], bh[nq][3],
                          so + L::BH + boff);
                if (B_LO)
                    ldsm_x4_t(bl[nq][0], bl[nq][1], bl[nq][2], bl[nq][3],
                              so + L::BL + boff);
            }
            // ---- term-major MMA issue: same-acc reuse distance = 16 ----
            // term HH
#pragma unroll
            for (int nq = 0; nq < 4; nq++)
#pragma unroll
                for (int h = 0; h < 2; h++)
#pragma unroll
                    for (int mf = 0; mf < 2; mf++)
                        mma16816(acc[mf][nq * 2 + h], ah[mf], bh[nq][h * 2],
                                 bh[nq][h * 2 + 1]);
            // term HL
            if (B_LO) {
#pragma unroll
                for (int nq = 0; nq < 4; nq++)
#pragma unroll
                    for (int h = 0; h < 2; h++)
#pragma unroll
                        for (int mf = 0; mf < 2; mf++)
                            mma16816(acc[mf][nq * 2 + h], ah[mf],
                                     bl[nq][h * 2], bl[nq][h * 2 + 1]);
            }
            // term LH
            if (A_LO) {
#pragma unroll
                for (int nq = 0; nq < 4; nq++)
#pragma unroll
                    for (int h = 0; h < 2; h++)
#pragma unroll
                        for (int mf = 0; mf < 2; mf++)
                            mma16816(acc[mf][nq * 2 + h], al[mf],
                                     bh[nq][h * 2], bh[nq][h * 2 + 1]);
            }
        }
    }

    // ---- epilogue ----
    const float* bias = nullptr;
    if (QKV) bias = (z == 0) ? b0 : (z == 1) ? b1 : b2;
#pragma unroll
    for (int mf = 0; mf < 2; mf++) {
#pragma unroll
        for (int nf = 0; nf < 8; nf++) {
            const int m = bm + wm * 32 + mf * 16 + (lane >> 2);
            const int n = bn + wn * 64 + nf * 8 + (lane & 3) * 2;
            float2 v0, v1;
            v0.x = acc[mf][nf][0] * alpha;
            v0.y = acc[mf][nf][1] * alpha;
            v1.x = acc[mf][nf][2] * alpha;
            v1.y = acc[mf][nf][3] * alpha;
            if (QKV) {
                v0.x += bias[n]; v0.y += bias[n + 1];
                v1.x += bias[n]; v1.y += bias[n + 1];
                const size_t o0 = (size_t)z * sC + (size_t)m * N + n;
                const size_t o1 = (size_t)z * sC + (size_t)(m + 8) * N + n;
                __half2 h0 = __floats2half2_rn(v0.x, v0.y);
                __half2 h1 = __floats2half2_rn(v1.x, v1.y);
                float2 f0 = __half22float2(h0);
                float2 f1 = __half22float2(h1);
                __half2 l0 = __floats2half2_rn(v0.x - f0.x, v0.y - f0.y);
                __half2 l1 = __floats2half2_rn(v1.x - f1.x, v1.y - f1.y);
                *reinterpret_cast<__half2*>(Ch + o0) = h0;
                *reinterpret_cast<__half2*>(Cl + o0) = l0;
                *reinterpret_cast<__half2*>(Ch + o1) = h1;
                *reinterpret_cast<__half2*>(Cl + o1) = l1;
            } else {
                float* c = Cf + (size_t)z * sC;
                *reinterpret_cast<float2*>(c + (size_t)m * N + n) = v0;
                *reinterpret_cast<float2*>(c + (size_t)(m + 8) * N + n) = v1;
            }
        }
    }
}

// ---------------- elementwise fp32 -> fp16 hi/lo split ----------------
__global__ void __launch_bounds__(256) split_kernel(
    const float* __restrict__ in, __half* __restrict__ hi,
    __half* __restrict__ lo, int n4) {
    const int i = blockIdx.x * 256 + threadIdx.x;
    if (i >= n4) return;
    const float4 v = reinterpret_cast<const float4*>(in)[i];
    __half2 h0 = __floats2half2_rn(v.x, v.y);
    __half2 h1 = __floats2half2_rn(v.z, v.w);
    float2 f0 = __half22float2(h0);
    float2 f1 = __half22float2(h1);
    __half2 l0 = __floats2half2_rn(v.x - f0.x, v.y - f0.y);
    __half2 l1 = __floats2half2_rn(v.z - f1.x, v.w - f1.y);
    reinterpret_cast<__half2*>(hi)[i * 2 + 0] = h0;
    reinterpret_cast<__half2*>(hi)[i * 2 + 1] = h1;
    reinterpret_cast<__half2*>(lo)[i * 2 + 0] = l0;
    reinterpret_cast<__half2*>(lo)[i * 2 + 1] = l1;
}

// ---------------- fp16 transpose, 32x32 tiles, per-batch ----------------
__global__ void __launch_bounds__(256) transposeH(
    const __half* __restrict__ in, __half* __restrict__ out, int R, int C) {
    __shared__ __half t[32][33];
    const int z = blockIdx.z;
    in += (size_t)z * R * C;
    out += (size_t)z * R * C;
    const int r0 = blockIdx.y * 32, c0 = blockIdx.x * 32;
    const int tx = threadIdx.x, ty = threadIdx.y;
#pragma unroll
    for (int i = 0; i < 4; i++)
        t[ty + i * 8][tx] = in[(size_t)(r0 + ty + i * 8) * C + c0 + tx];
    __syncthreads();
#pragma unroll
    for (int i = 0; i < 4; i++)
        out[(size_t)(c0 + ty + i * 8) * R + r0 + tx] = t[tx][ty + i * 8];
}

// ---------------- softmax: fp32 P row -> fp16 hi P row ----------------
__global__ void __launch_bounds__(256) softmax_kernel() {
    const float* row = g_P + (size_t)blockIdx.x * SS;
    __half* orow = g_Ph + (size_t)blockIdx.x * SS;
    const int tid = threadIdx.x;
    const int lane = tid & 31;
    const int wid = tid >> 5;
    __shared__ float red[8];

    float v[8];
    float m = -1e30f;
#pragma unroll
    for (int i = 0; i < 8; i++) {
        v[i] = row[tid + i * 256];
        m = fmaxf(m, v[i]);
    }
#pragma unroll
    for (int o = 16; o > 0; o >>= 1)
        m = fmaxf(m, __shfl_xor_sync(0xffffffffu, m, o));
    if (lane == 0) red[wid] = m;
    __syncthreads();
    m = red[0];
#pragma unroll
    for (int w = 1; w < 8; w++) m = fmaxf(m, red[w]);
    __syncthreads();

    float s = 0.0f;
#pragma unroll
    for (int i = 0; i < 8; i++) {
        v[i] = expf(v[i] - m);
        s += v[i];
    }
#pragma unroll
    for (int o = 16; o > 0; o >>= 1) s += __shfl_xor_sync(0xffffffffu, s, o);
    if (lane == 0) red[wid] = s;
    __syncthreads();
    s = red[0];
#pragma unroll
    for (int w = 1; w < 8; w++) s += red[w];
    const float inv = 1.0f / s;
#pragma unroll
    for (int i = 0; i < 8; i++)
        orow[tid + i * 256] = __float2half_rn(v[i] * inv);
}

// ---------------- launch ----------------
extern "C" void kernel_launch(void* const* d_in, const int* in_sizes, int n_in,
                              void* d_out, int out_size) {
    const float* x  = (const float*)d_in[0];
    const float* Wq = (const float*)d_in[1];
    const float* bq = (const float*)d_in[2];
    const float* Wk = (const float*)d_in[3];
    const float* bk = (const float*)d_in[4];
    const float* Wv = (const float*)d_in[5];
    const float* bv = (const float*)d_in[6];
    float* out = (float*)d_out;

    __half *xh, *xl, *wh, *wl, *qkvh, *qkvl, *kth, *ktl, *ph;
    float* p;
    cudaGetSymbolAddress((void**)&xh, gx_hi);
    cudaGetSymbolAddress((void**)&xl, gx_lo);
    cudaGetSymbolAddress((void**)&wh, gw_hi);
    cudaGetSymbolAddress((void**)&wl, gw_lo);
    cudaGetSymbolAddress((void**)&qkvh, gqkv_hi);
    cudaGetSymbolAddress((void**)&qkvl, gqkv_lo);
    cudaGetSymbolAddress((void**)&kth, gkT_hi);
    cudaGetSymbolAddress((void**)&ktl, gkT_lo);
    cudaGetSymbolAddress((void**)&p, g_P);
    cudaGetSymbolAddress((void**)&ph, g_Ph);

    constexpr int SM3 = SL<true, true>::BYTES * STAGES;   // 192KB
    constexpr int SM2 = SL<false, true>::BYTES * STAGES;  // 144KB
    cudaFuncSetAttribute(hgemm<true, true, true>,
                         cudaFuncAttributeMaxDynamicSharedMemorySize, SM3);
    cudaFuncSetAttribute(hgemm<false, true, false>,
                         cudaFuncAttributeMaxDynamicSharedMemorySize, SM2);

    // 1) split inputs to fp16 hi/lo
    split_kernel<<<(int)(BSD / 4 / 256), 256>>>(x, xh, xl, (int)(BSD / 4));
    const int wn4 = DD * DD / 4;
    split_kernel<<<wn4 / 256, 256>>>(Wq, wh + 0ull * DD * DD, wl + 0ull * DD * DD, wn4);
    split_kernel<<<wn4 / 256, 256>>>(Wk, wh + 1ull * DD * DD, wl + 1ull * DD * DD, wn4);
    split_kernel<<<wn4 / 256, 256>>>(Wv, wh + 2ull * DD * DD, wl + 2ull * DD * DD, wn4);

    // 2) QKV: C[16384,1024] = x @ W + bias (3-term)
    hgemm<true, true, true><<<dim3(DD / BN, (BB * SS) / BM, 3), NTH, SM3>>>(
        xh, xl, wh, wl, nullptr, qkvh, qkvl, DD, DD,
        0LL, (long long)DD * DD, (long long)BSD, 1.0f, bq, bk, bv);

    // 3) K^T per batch: [2048,1024] -> [1024,2048], hi and lo
    dim3 tb(32, 8);
    transposeH<<<dim3(DD / 32, SS / 32, BB), tb>>>(qkvh + BSD, kth, SS, DD);
    transposeH<<<dim3(DD / 32, SS / 32, BB), tb>>>(qkvl + BSD, ktl, SS, DD);

    // 4) scores: P[b] = (Q[b] @ K[b]^T) / 32, 2-term (Qhi·Khi + Qhi·Klo)
    hgemm<false, true, false><<<dim3(SS / BN, SS / BM, BB), NTH, SM2>>>(
        qkvh, nullptr, kth, ktl, p, nullptr, nullptr, SS, DD,
        (long long)SS * DD, (long long)DD * SS, (long long)SS * SS,
        0.03125f, nullptr, nullptr, nullptr);

    // 5) softmax (fp32 in, fp16-hi out)
    softmax_kernel<<<BB * SS, 256>>>();

    // 6) out[b] = P[b] @ V[b], 2-term (Phi·Vhi + Phi·Vlo)
    hgemm<false, true, false><<<dim3(DD / BN, SS / BM, BB), NTH, SM2>>>(
        ph, nullptr, qkvh + 2 * BSD, qkvl + 2 * BSD, out, nullptr, nullptr,
        DD, SS, (long long)SS * SS, (long long)SS * DD, (long long)SS * DD,
        1.0f, nullptr, nullptr, nullptr);
}

// round 6
// speedup vs baseline: 4.4168x; 1.3229x over previous
#include <cuda_runtime.h>
#include <cuda_fp16.h>
#include <math.h>
#include <stdint.h>

// Problem shape (fixed by the reference)
#define BB 8
#define SS 2048
#define DD 1024

constexpr size_t BSD = (size_t)BB * SS * DD;   // 16M elems

// ---------------- device scratch (allocation-free rule) ----------------
__device__ __half gx_hi[BSD];
__device__ __half gw_hi[3ull * DD * DD], gw_lo[3ull * DD * DD];
__device__ __half gqkv_hi[3ull * BB * SS * DD], gqkv_lo[3ull * BB * SS * DD];
__device__ __half gkT_hi[BSD], gkT_lo[BSD];
__device__ float g_P[(size_t)BB * SS * SS];
__device__ __half g_Ph[(size_t)BB * SS * SS];

// ---------------- PTX helpers ----------------
__device__ __forceinline__ void ldsm_x4(uint32_t& r0, uint32_t& r1,
                                        uint32_t& r2, uint32_t& r3,
                                        uint32_t addr) {
    asm volatile(
        "ldmatrix.sync.aligned.m8n8.x4.shared.b16 {%0,%1,%2,%3}, [%4];\n"
        : "=r"(r0), "=r"(r1), "=r"(r2), "=r"(r3)
        : "r"(addr));
}

__device__ __forceinline__ void ldsm_x4_t(uint32_t& r0, uint32_t& r1,
                                          uint32_t& r2, uint32_t& r3,
                                          uint32_t addr) {
    asm volatile(
        "ldmatrix.sync.aligned.m8n8.x4.trans.shared.b16 {%0,%1,%2,%3}, [%4];\n"
        : "=r"(r0), "=r"(r1), "=r"(r2), "=r"(r3)
        : "r"(addr));
}

__device__ __forceinline__ void mma16816(float* c, const uint32_t* a,
                                         uint32_t b0, uint32_t b1) {
    asm volatile(
        "mma.sync.aligned.m16n8k16.row.col.f32.f16.f16.f32 "
        "{%0,%1,%2,%3}, {%4,%5,%6,%7}, {%8,%9}, {%0,%1,%2,%3};\n"
        : "+f"(c[0]), "+f"(c[1]), "+f"(c[2]), "+f"(c[3])
        : "r"(a[0]), "r"(a[1]), "r"(a[2]), "r"(a[3]), "r"(b0), "r"(b1));
}

__device__ __forceinline__ void cp16(uint32_t dst, const void* src) {
    asm volatile("cp.async.cg.shared.global [%0], [%1], 16;\n" ::"r"(dst),
                 "l"(src)
                 : "memory");
}
#define CP_COMMIT() asm volatile("cp.async.commit_group;\n" ::: "memory")
#define CP_WAIT1() asm volatile("cp.async.wait_group 1;\n" ::: "memory")
#define CP_WAIT0() asm volatile("cp.async.wait_group 0;\n" ::: "memory")

#define SWZ(x) ((uint32_t)(x) ^ ((((uint32_t)(x)) >> 3) & 0x70))

// ---------------- GEMM config ----------------
constexpr int BM = 128, BN = 128, BK = 64, NTH = 256, STAGES = 2;
// stage layout (bytes): A_hi 16K | B_hi 16K | B_lo 16K
constexpr int AH_OFF = 0, BH_OFF = 16384, BL_OFF = 32768;
constexpr int STAGE_BYTES = 49152;
constexpr int GEMM_SMEM = STAGES * STAGE_BYTES;  // 96KB -> 2 CTAs/SM

// C[M,N] = alpha * (A_hi[M,K] @ (B_hi+B_lo)[K,N]) (+bias / split-out).
// All fp16 row-major operands; dims multiples of tile sizes. z = batch idx.
template <bool QKV>
__global__ void __launch_bounds__(NTH, 2) hgemm(
    const __half* __restrict__ Ah, const __half* __restrict__ Bh,
    const __half* __restrict__ Bl, float* __restrict__ Cf,
    __half* __restrict__ Ch, __half* __restrict__ Cl, int N, int K,
    long long sA, long long sB, long long sC, float alpha,
    const float* __restrict__ b0, const float* __restrict__ b1,
    const float* __restrict__ b2) {
    extern __shared__ char smem[];
    const uint32_t sb = (uint32_t)__cvta_generic_to_shared(smem);
    const int tid = threadIdx.x, lane = tid & 31, warp = tid >> 5;
    const int wm = warp >> 1, wn = warp & 1;
    const int z = blockIdx.z;
    const int bm = blockIdx.y * BM, bn = blockIdx.x * BN;

    const __half* Agh = Ah + (size_t)z * sA + (size_t)bm * K;
    const __half* Bgh = Bh + (size_t)z * sB;
    const __half* Bgl = Bl + (size_t)z * sB;

    auto issue = [&](int s) {
        const uint32_t so = sb + (uint32_t)(s & 1) * STAGE_BYTES;
        const int k0 = s * BK;
#pragma unroll
        for (int i = 0; i < 4; i++) {
            const int idx = tid + i * NTH;
            const int row = idx >> 3, c = idx & 7;
            cp16(so + AH_OFF + SWZ(row * 128 + c * 16),
                 Agh + (size_t)row * K + k0 + c * 8);
        }
#pragma unroll
        for (int i = 0; i < 4; i++) {
            const int idx = tid + i * NTH;
            const int krow = idx >> 4, sub = (idx >> 3) & 1, c = idx & 7;
            const size_t g = (size_t)(k0 + krow) * N + bn + sub * 64 + c * 8;
            const uint32_t d = (uint32_t)sub * 8192 + SWZ(krow * 128 + c * 16);
            cp16(so + BH_OFF + d, Bgh + g);
            cp16(so + BL_OFF + d, Bgl + g);
        }
        CP_COMMIT();
    };

    float acc[2][8][4];
#pragma unroll
    for (int i = 0; i < 2; i++)
#pragma unroll
        for (int j = 0; j < 8; j++)
#pragma unroll
            for (int q = 0; q < 4; q++) acc[i][j][q] = 0.0f;

    const int ns = K / BK;
    issue(0);
    issue(1);
    for (int s = 0; s < ns; s++) {
        if (s == ns - 1) { CP_WAIT0(); } else { CP_WAIT1(); }
        __syncthreads();
        const uint32_t so = sb + (uint32_t)(s & 1) * STAGE_BYTES;
#pragma unroll
        for (int kf = 0; kf < 4; kf++) {
            // preload all fragments for this k16 slice
            uint32_t ah[2][4], bh[4][4], bl[4][4];
#pragma unroll
            for (int mf = 0; mf < 2; mf++) {
                const int rowA = wm * 32 + mf * 16 + (lane & 15);
                const int col2 = (kf * 16 + (lane >> 4) * 8) * 2;
                ldsm_x4(ah[mf][0], ah[mf][1], ah[mf][2], ah[mf][3],
                        so + AH_OFF + SWZ(rowA * 128 + col2));
            }
#pragma unroll
            for (int nq = 0; nq < 4; nq++) {
                const int krow = kf * 16 + (lane & 15);
                const int nloc2 = (nq * 16 + (lane >> 4) * 8) * 2;
                const uint32_t boff =
                    (uint32_t)wn * 8192 + SWZ(krow * 128 + nloc2);
                ldsm_x4_t(bh[nq][0], bh[nq][1], bh[nq][2], bh[nq][3],
                          so + BH_OFF + boff);
                ldsm_x4_t(bl[nq][0], bl[nq][1], bl[nq][2], bl[nq][3],
                          so + BL_OFF + boff);
            }
            // term-major: HH across all 16 accs, then HL
#pragma unroll
            for (int nq = 0; nq < 4; nq++)
#pragma unroll
                for (int h = 0; h < 2; h++)
#pragma unroll
                    for (int mf = 0; mf < 2; mf++)
                        mma16816(acc[mf][nq * 2 + h], ah[mf], bh[nq][h * 2],
                                 bh[nq][h * 2 + 1]);
#pragma unroll
            for (int nq = 0; nq < 4; nq++)
#pragma unroll
                for (int h = 0; h < 2; h++)
#pragma unroll
                    for (int mf = 0; mf < 2; mf++)
                        mma16816(acc[mf][nq * 2 + h], ah[mf], bl[nq][h * 2],
                                 bl[nq][h * 2 + 1]);
        }
        __syncthreads();  // all reads of buffer s&1 done before refill
        if (s + 2 < ns) issue(s + 2);
    }

    // ---- epilogue ----
    const float* bias = nullptr;
    if (QKV) bias = (z == 0) ? b0 : (z == 1) ? b1 : b2;
#pragma unroll
    for (int mf = 0; mf < 2; mf++) {
#pragma unroll
        for (int nf = 0; nf < 8; nf++) {
            const int m = bm + wm * 32 + mf * 16 + (lane >> 2);
            const int n = bn + wn * 64 + nf * 8 + (lane & 3) * 2;
            float2 v0, v1;
            v0.x = acc[mf][nf][0] * alpha;
            v0.y = acc[mf][nf][1] * alpha;
            v1.x = acc[mf][nf][2] * alpha;
            v1.y = acc[mf][nf][3] * alpha;
            if (QKV) {
                v0.x += bias[n]; v0.y += bias[n + 1];
                v1.x += bias[n]; v1.y += bias[n + 1];
                const size_t o0 = (size_t)z * sC + (size_t)m * N + n;
                const size_t o1 = (size_t)z * sC + (size_t)(m + 8) * N + n;
                __half2 h0 = __floats2half2_rn(v0.x, v0.y);
                __half2 h1 = __floats2half2_rn(v1.x, v1.y);
                float2 f0 = __half22float2(h0);
                float2 f1 = __half22float2(h1);
                __half2 l0 = __floats2half2_rn(v0.x - f0.x, v0.y - f0.y);
                __half2 l1 = __floats2half2_rn(v1.x - f1.x, v1.y - f1.y);
                *reinterpret_cast<__half2*>(Ch + o0) = h0;
                *reinterpret_cast<__half2*>(Cl + o0) = l0;
                *reinterpret_cast<__half2*>(Ch + o1) = h1;
                *reinterpret_cast<__half2*>(Cl + o1) = l1;
            } else {
                float* c = Cf + (size_t)z * sC;
                *reinterpret_cast<float2*>(c + (size_t)m * N + n) = v0;
                *reinterpret_cast<float2*>(c + (size_t)(m + 8) * N + n) = v1;
            }
        }
    }
}

// ---------------- fp32 -> fp16 hi (+optional lo) ----------------
__global__ void __launch_bounds__(256) split_kernel(
    const float* __restrict__ in, __half* __restrict__ hi,
    __half* __restrict__ lo, int n4) {
    const int i = blockIdx.x * 256 + threadIdx.x;
    if (i >= n4) return;
    const float4 v = reinterpret_cast<const float4*>(in)[i];
    __half2 h0 = __floats2half2_rn(v.x, v.y);
    __half2 h1 = __floats2half2_rn(v.z, v.w);
    reinterpret_cast<__half2*>(hi)[i * 2 + 0] = h0;
    reinterpret_cast<__half2*>(hi)[i * 2 + 1] = h1;
    if (lo) {
        float2 f0 = __half22float2(h0);
        float2 f1 = __half22float2(h1);
        __half2 l0 = __floats2half2_rn(v.x - f0.x, v.y - f0.y);
        __half2 l1 = __floats2half2_rn(v.z - f1.x, v.w - f1.y);
        reinterpret_cast<__half2*>(lo)[i * 2 + 0] = l0;
        reinterpret_cast<__half2*>(lo)[i * 2 + 1] = l1;
    }
}

// ---------------- fp16 transpose, 32x32 tiles, per-batch ----------------
__global__ void __launch_bounds__(256) transposeH(
    const __half* __restrict__ in, __half* __restrict__ out, int R, int C) {
    __shared__ __half t[32][33];
    const int z = blockIdx.z;
    in += (size_t)z * R * C;
    out += (size_t)z * R * C;
    const int r0 = blockIdx.y * 32, c0 = blockIdx.x * 32;
    const int tx = threadIdx.x, ty = threadIdx.y;
#pragma unroll
    for (int i = 0; i < 4; i++)
        t[ty + i * 8][tx] = in[(size_t)(r0 + ty + i * 8) * C + c0 + tx];
    __syncthreads();
#pragma unroll
    for (int i = 0; i < 4; i++)
        out[(size_t)(c0 + ty + i * 8) * R + r0 + tx] = t[tx][ty + i * 8];
}

// ---------------- softmax: fp32 P row -> fp16 hi P row ----------------
__global__ void __launch_bounds__(256) softmax_kernel() {
    const float* row = g_P + (size_t)blockIdx.x * SS;
    __half* orow = g_Ph + (size_t)blockIdx.x * SS;
    const int tid = threadIdx.x;
    const int lane = tid & 31;
    const int wid = tid >> 5;
    __shared__ float red[8];

    float v[8];
    float m = -1e30f;
#pragma unroll
    for (int i = 0; i < 8; i++) {
        v[i] = row[tid + i * 256];
        m = fmaxf(m, v[i]);
    }
#pragma unroll
    for (int o = 16; o > 0; o >>= 1)
        m = fmaxf(m, __shfl_xor_sync(0xffffffffu, m, o));
    if (lane == 0) red[wid] = m;
    __syncthreads();
    m = red[0];
#pragma unroll
    for (int w = 1; w < 8; w++) m = fmaxf(m, red[w]);
    __syncthreads();

    float s = 0.0f;
#pragma unroll
    for (int i = 0; i < 8; i++) {
        v[i] = expf(v[i] - m);
        s += v[i];
    }
#pragma unroll
    for (int o = 16; o > 0; o >>= 1) s += __shfl_xor_sync(0xffffffffu, s, o);
    if (lane == 0) red[wid] = s;
    __syncthreads();
    s = red[0];
#pragma unroll
    for (int w = 1; w < 8; w++) s += red[w];
    const float inv = 1.0f / s;
#pragma unroll
    for (int i = 0; i < 8; i++)
        orow[tid + i * 256] = __float2half_rn(v[i] * inv);
}

// ---------------- launch ----------------
extern "C" void kernel_launch(void* const* d_in, const int* in_sizes, int n_in,
                              void* d_out, int out_size) {
    const float* x  = (const float*)d_in[0];
    const float* Wq = (const float*)d_in[1];
    const float* bq = (const float*)d_in[2];
    const float* Wk = (const float*)d_in[3];
    const float* bk = (const float*)d_in[4];
    const float* Wv = (const float*)d_in[5];
    const float* bv = (const float*)d_in[6];
    float* out = (float*)d_out;

    __half *xh, *wh, *wl, *qkvh, *qkvl, *kth, *ktl, *ph;
    float* p;
    cudaGetSymbolAddress((void**)&xh, gx_hi);
    cudaGetSymbolAddress((void**)&wh, gw_hi);
    cudaGetSymbolAddress((void**)&wl, gw_lo);
    cudaGetSymbolAddress((void**)&qkvh, gqkv_hi);
    cudaGetSymbolAddress((void**)&qkvl, gqkv_lo);
    cudaGetSymbolAddress((void**)&kth, gkT_hi);
    cudaGetSymbolAddress((void**)&ktl, gkT_lo);
    cudaGetSymbolAddress((void**)&p, g_P);
    cudaGetSymbolAddress((void**)&ph, g_Ph);

    cudaFuncSetAttribute(hgemm<true>,
                         cudaFuncAttributeMaxDynamicSharedMemorySize, GEMM_SMEM);
    cudaFuncSetAttribute(hgemm<false>,
                         cudaFuncAttributeMaxDynamicSharedMemorySize, GEMM_SMEM);

    // 1) x -> fp16 hi only; W -> hi/lo split
    split_kernel<<<(int)(BSD / 4 / 256), 256>>>(x, xh, nullptr, (int)(BSD / 4));
    const int wn4 = DD * DD / 4;
    split_kernel<<<wn4 / 256, 256>>>(Wq, wh + 0ull * DD * DD, wl + 0ull * DD * DD, wn4);
    split_kernel<<<wn4 / 256, 256>>>(Wk, wh + 1ull * DD * DD, wl + 1ull * DD * DD, wn4);
    split_kernel<<<wn4 / 256, 256>>>(Wv, wh + 2ull * DD * DD, wl + 2ull * DD * DD, wn4);

    // 2) QKV: C[16384,1024] = x_hi @ (W_hi + W_lo) + bias
    hgemm<true><<<dim3(DD / BN, (BB * SS) / BM, 3), NTH, GEMM_SMEM>>>(
        xh, wh, wl, nullptr, qkvh, qkvl, DD, DD,
        0LL, (long long)DD * DD, (long long)BSD, 1.0f, bq, bk, bv);

    // 3) K^T per batch: [2048,1024] -> [1024,2048], hi and lo
    dim3 tb(32, 8);
    transposeH<<<dim3(DD / 32, SS / 32, BB), tb>>>(qkvh + BSD, kth, SS, DD);
    transposeH<<<dim3(DD / 32, SS / 32, BB), tb>>>(qkvl + BSD, ktl, SS, DD);

    // 4) scores: P[b] = Q_hi[b] @ (K^T_hi + K^T_lo)[b] / 32
    hgemm<false><<<dim3(SS / BN, SS / BM, BB), NTH, GEMM_SMEM>>>(
        qkvh, kth, ktl, p, nullptr, nullptr, SS, DD,
        (long long)SS * DD, (long long)DD * SS, (long long)SS * SS,
        0.03125f, nullptr, nullptr, nullptr);

    // 5) softmax (fp32 in, fp16-hi out)
    softmax_kernel<<<BB * SS, 256>>>();

    // 6) out[b] = P_hi[b] @ (V_hi + V_lo)[b]
    hgemm<false><<<dim3(DD / BN, SS / BM, BB), NTH, GEMM_SMEM>>>(
        ph, qkvh + 2 * BSD, qkvl + 2 * BSD, out, nullptr, nullptr,
        DD, SS, (long long)SS * SS, (long long)SS * DD, (long long)SS * DD,
        1.0f, nullptr, nullptr, nullptr);
}

// round 7
// speedup vs baseline: 4.4230x; 1.0014x over previous
#include <cuda_runtime.h>
#include <cuda_fp16.h>
#include <math.h>
#include <stdint.h>

// Problem shape (fixed by the reference)
#define BB 8
#define SS 2048
#define DD 1024

constexpr size_t BSD = (size_t)BB * SS * DD;   // 16M elems

// ---------------- device scratch (allocation-free rule) ----------------
__device__ __half gx_hi[BSD];
__device__ __half gw_hi[3ull * DD * DD], gw_lo[3ull * DD * DD];
__device__ __half gqkv_hi[3ull * BB * SS * DD], gqkv_lo[3ull * BB * SS * DD];
__device__ float g_P[(size_t)BB * SS * SS];
__device__ __half g_Ph[(size_t)BB * SS * SS];

// ---------------- PTX helpers ----------------
__device__ __forceinline__ void ldsm_x4(uint32_t& r0, uint32_t& r1,
                                        uint32_t& r2, uint32_t& r3,
                                        uint32_t addr) {
    asm volatile(
        "ldmatrix.sync.aligned.m8n8.x4.shared.b16 {%0,%1,%2,%3}, [%4];\n"
        : "=r"(r0), "=r"(r1), "=r"(r2), "=r"(r3)
        : "r"(addr));
}

__device__ __forceinline__ void ldsm_x4_t(uint32_t& r0, uint32_t& r1,
                                          uint32_t& r2, uint32_t& r3,
                                          uint32_t addr) {
    asm volatile(
        "ldmatrix.sync.aligned.m8n8.x4.trans.shared.b16 {%0,%1,%2,%3}, [%4];\n"
        : "=r"(r0), "=r"(r1), "=r"(r2), "=r"(r3)
        : "r"(addr));
}

__device__ __forceinline__ void mma16816(float* c, const uint32_t* a,
                                         uint32_t b0, uint32_t b1) {
    asm volatile(
        "mma.sync.aligned.m16n8k16.row.col.f32.f16.f16.f32 "
        "{%0,%1,%2,%3}, {%4,%5,%6,%7}, {%8,%9}, {%0,%1,%2,%3};\n"
        : "+f"(c[0]), "+f"(c[1]), "+f"(c[2]), "+f"(c[3])
        : "r"(a[0]), "r"(a[1]), "r"(a[2]), "r"(a[3]), "r"(b0), "r"(b1));
}

__device__ __forceinline__ void cp16(uint32_t dst, const void* src) {
    asm volatile("cp.async.cg.shared.global [%0], [%1], 16;\n" ::"r"(dst),
                 "l"(src)
                 : "memory");
}
#define CP_COMMIT() asm volatile("cp.async.commit_group;\n" ::: "memory")
#define CP_WAIT1() asm volatile("cp.async.wait_group 1;\n" ::: "memory")
#define CP_WAIT0() asm volatile("cp.async.wait_group 0;\n" ::: "memory")

#define SWZ(x) ((uint32_t)(x) ^ ((((uint32_t)(x)) >> 3) & 0x70))

// ---------------- GEMM config ----------------
constexpr int BM = 128, BN = 128, BK = 64, NTH = 256, STAGES = 2;
// stage layout (bytes): A_hi 16K | B_hi 16K | B_lo 16K
constexpr int AH_OFF = 0, BH_OFF = 16384, BL_OFF = 32768;
constexpr int STAGE_BYTES = 49152;
constexpr int GEMM_SMEM = STAGES * STAGE_BYTES;  // 96KB -> 2 CTAs/SM

// C[M,N] = alpha * (A_hi[M,K] @ (B_hi+B_lo)) (+bias / split-out for QKV).
// BNK=0: B stored [K,N] row-major (trans-ldsm path).
// BNK=1: B stored [N,K] row-major (A-style non-trans ldsm path).
// Warp grid 2x4: warp tile 64x32 (minimizes smem re-reads for 2-term B).
template <int BNK, bool QKV>
__global__ void __launch_bounds__(NTH, 2) hgemm(
    const __half* __restrict__ Ah, const __half* __restrict__ Bh,
    const __half* __restrict__ Bl, float* __restrict__ Cf,
    __half* __restrict__ Ch, __half* __restrict__ Cl, int N, int K,
    long long sA, long long sB, long long sC, float alpha,
    const float* __restrict__ b0, const float* __restrict__ b1,
    const float* __restrict__ b2) {
    extern __shared__ char smem[];
    const uint32_t sb = (uint32_t)__cvta_generic_to_shared(smem);
    const int tid = threadIdx.x, lane = tid & 31, warp = tid >> 5;
    const int wm = warp >> 2;   // 0..1 -> 64 rows each
    const int wn = warp & 3;    // 0..3 -> 32 cols each
    const int z = blockIdx.z;
    const int bm = blockIdx.y * BM, bn = blockIdx.x * BN;

    const __half* Agh = Ah + (size_t)z * sA + (size_t)bm * K;
    const __half* Bgh = Bh + (size_t)z * sB;
    const __half* Bgl = Bl + (size_t)z * sB;

    auto issue = [&](int s) {
        const uint32_t so = sb + (uint32_t)(s & 1) * STAGE_BYTES;
        const int k0 = s * BK;
#pragma unroll
        for (int i = 0; i < 4; i++) {
            const int idx = tid + i * NTH;
            const int row = idx >> 3, c = idx & 7;
            cp16(so + AH_OFF + SWZ(row * 128 + c * 16),
                 Agh + (size_t)row * K + k0 + c * 8);
        }
        if (BNK) {
            // B [N,K]: same pattern as A, rows are n
#pragma unroll
            for (int i = 0; i < 4; i++) {
                const int idx = tid + i * NTH;
                const int row = idx >> 3, c = idx & 7;
                const size_t g = (size_t)(bn + row) * K + k0 + c * 8;
                const uint32_t d = SWZ(row * 128 + c * 16);
                cp16(so + BH_OFF + d, Bgh + g);
                cp16(so + BL_OFF + d, Bgl + g);
            }
        } else {
            // B [K,N]: 64 k-rows x 128 n-cols, split into two 64-col halves
#pragma unroll
            for (int i = 0; i < 4; i++) {
                const int idx = tid + i * NTH;
                const int krow = idx >> 4, sub = (idx >> 3) & 1, c = idx & 7;
                const size_t g = (size_t)(k0 + krow) * N + bn + sub * 64 + c * 8;
                const uint32_t d = (uint32_t)sub * 8192 + SWZ(krow * 128 + c * 16);
                cp16(so + BH_OFF + d, Bgh + g);
                cp16(so + BL_OFF + d, Bgl + g);
            }
        }
        CP_COMMIT();
    };

    float acc[4][4][4];  // [mf][nf][quad]
#pragma unroll
    for (int i = 0; i < 4; i++)
#pragma unroll
        for (int j = 0; j < 4; j++)
#pragma unroll
            for (int q = 0; q < 4; q++) acc[i][j][q] = 0.0f;

    const int ns = K / BK;
    issue(0);
    issue(1);
    for (int s = 0; s < ns; s++) {
        if (s == ns - 1) { CP_WAIT0(); } else { CP_WAIT1(); }
        __syncthreads();
        const uint32_t so = sb + (uint32_t)(s & 1) * STAGE_BYTES;
#pragma unroll
        for (int kf = 0; kf < 4; kf++) {
            // ---- A fragments: 4 x ldsm.x4 (m = wm*64 .. +64) ----
            uint32_t ah[4][4];
#pragma unroll
            for (int mf = 0; mf < 4; mf++) {
                const int rowA = wm * 64 + mf * 16 + (lane & 15);
                const int col2 = (kf * 16 + (lane >> 4) * 8) * 2;
                ldsm_x4(ah[mf][0], ah[mf][1], ah[mf][2], ah[mf][3],
                        so + AH_OFF + SWZ(rowA * 128 + col2));
            }
            // ---- B fragments (hi + lo), n = wn*32 .. +32 ----
            uint32_t bh[2][4], bl[2][4];
#pragma unroll
            for (int nq = 0; nq < 2; nq++) {
                uint32_t boff;
                if (BNK) {
                    const int rowB = wn * 32 + nq * 16 + (lane & 15);
                    const int col2 = (kf * 16 + (lane >> 4) * 8) * 2;
                    boff = SWZ(rowB * 128 + col2);
                    ldsm_x4(bh[nq][0], bh[nq][1], bh[nq][2], bh[nq][3],
                            so + BH_OFF + boff);
                    ldsm_x4(bl[nq][0], bl[nq][1], bl[nq][2], bl[nq][3],
                            so + BL_OFF + boff);
                } else {
                    const int krow = kf * 16 + (lane & 15);
                    const int ncol = wn * 32 + nq * 16 + (lane >> 4) * 8;
                    boff = (uint32_t)(ncol >= 64) * 8192 +
                           SWZ(krow * 128 + (ncol & 63) * 2);
                    ldsm_x4_t(bh[nq][0], bh[nq][1], bh[nq][2], bh[nq][3],
                              so + BH_OFF + boff);
                    ldsm_x4_t(bl[nq][0], bl[nq][1], bl[nq][2], bl[nq][3],
                              so + BL_OFF + boff);
                }
            }
            // ---- term-major MMA: HH then HL across all 16 accs ----
            // fragment pairing differs by load path:
            //   trans ([K,N]):  h=0 -> (r0,r1), h=1 -> (r2,r3)
            //   NK    ([N,K]):  h=0 -> (r0,r2), h=1 -> (r1,r3)
#pragma unroll
            for (int nq = 0; nq < 2; nq++)
#pragma unroll
                for (int h = 0; h < 2; h++) {
                    const uint32_t p0 = BNK ? bh[nq][h] : bh[nq][h * 2];
                    const uint32_t p1 = BNK ? bh[nq][h + 2] : bh[nq][h * 2 + 1];
#pragma unroll
                    for (int mf = 0; mf < 4; mf++)
                        mma16816(acc[mf][nq * 2 + h], ah[mf], p0, p1);
                }
#pragma unroll
            for (int nq = 0; nq < 2; nq++)
#pragma unroll
                for (int h = 0; h < 2; h++) {
                    const uint32_t p0 = BNK ? bl[nq][h] : bl[nq][h * 2];
                    const uint32_t p1 = BNK ? bl[nq][h + 2] : bl[nq][h * 2 + 1];
#pragma unroll
                    for (int mf = 0; mf < 4; mf++)
                        mma16816(acc[mf][nq * 2 + h], ah[mf], p0, p1);
                }
        }
        __syncthreads();  // all reads of buffer s&1 done before refill
        if (s + 2 < ns) issue(s + 2);
    }

    // ---- epilogue ----
    const float* bias = nullptr;
    if (QKV) bias = (z == 0) ? b0 : (z == 1) ? b1 : b2;
#pragma unroll
    for (int mf = 0; mf < 4; mf++) {
#pragma unroll
        for (int nf = 0; nf < 4; nf++) {
            const int m = bm + wm * 64 + mf * 16 + (lane >> 2);
            const int n = bn + wn * 32 + nf * 8 + (lane & 3) * 2;
            float2 v0, v1;
            v0.x = acc[mf][nf][0] * alpha;
            v0.y = acc[mf][nf][1] * alpha;
            v1.x = acc[mf][nf][2] * alpha;
            v1.y = acc[mf][nf][3] * alpha;
            if (QKV) {
                v0.x += bias[n]; v0.y += bias[n + 1];
                v1.x += bias[n]; v1.y += bias[n + 1];
                const size_t o0 = (size_t)z * sC + (size_t)m * N + n;
                const size_t o1 = (size_t)z * sC + (size_t)(m + 8) * N + n;
                __half2 h0 = __floats2half2_rn(v0.x, v0.y);
                __half2 h1 = __floats2half2_rn(v1.x, v1.y);
                float2 f0 = __half22float2(h0);
                float2 f1 = __half22float2(h1);
                __half2 l0 = __floats2half2_rn(v0.x - f0.x, v0.y - f0.y);
                __half2 l1 = __floats2half2_rn(v1.x - f1.x, v1.y - f1.y);
                *reinterpret_cast<__half2*>(Ch + o0) = h0;
                *reinterpret_cast<__half2*>(Cl + o0) = l0;
                *reinterpret_cast<__half2*>(Ch + o1) = h1;
                *reinterpret_cast<__half2*>(Cl + o1) = l1;
            } else {
                float* c = Cf + (size_t)z * sC;
                *reinterpret_cast<float2*>(c + (size_t)m * N + n) = v0;
                *reinterpret_cast<float2*>(c + (size_t)(m + 8) * N + n) = v1;
            }
        }
    }
}

// ---------------- fp32 -> fp16 hi (+optional lo) ----------------
__global__ void __launch_bounds__(256) split_kernel(
    const float* __restrict__ in, __half* __restrict__ hi,
    __half* __restrict__ lo, int n4) {
    const int i = blockIdx.x * 256 + threadIdx.x;
    if (i >= n4) return;
    const float4 v = reinterpret_cast<const float4*>(in)[i];
    __half2 h0 = __floats2half2_rn(v.x, v.y);
    __half2 h1 = __floats2half2_rn(v.z, v.w);
    reinterpret_cast<__half2*>(hi)[i * 2 + 0] = h0;
    reinterpret_cast<__half2*>(hi)[i * 2 + 1] = h1;
    if (lo) {
        float2 f0 = __half22float2(h0);
        float2 f1 = __half22float2(h1);
        __half2 l0 = __floats2half2_rn(v.x - f0.x, v.y - f0.y);
        __half2 l1 = __floats2half2_rn(v.z - f1.x, v.w - f1.y);
        reinterpret_cast<__half2*>(lo)[i * 2 + 0] = l0;
        reinterpret_cast<__half2*>(lo)[i * 2 + 1] = l1;
    }
}

// ---------------- softmax: fp32 P row -> fp16 hi P row ----------------
__global__ void __launch_bounds__(256) softmax_kernel() {
    const float* row = g_P + (size_t)blockIdx.x * SS;
    __half* orow = g_Ph + (size_t)blockIdx.x * SS;
    const int tid = threadIdx.x;
    const int lane = tid & 31;
    const int wid = tid >> 5;
    __shared__ float red[8];

    float v[8];
    float m = -1e30f;
#pragma unroll
    for (int i = 0; i < 8; i++) {
        v[i] = row[tid + i * 256];
        m = fmaxf(m, v[i]);
    }
#pragma unroll
    for (int o = 16; o > 0; o >>= 1)
        m = fmaxf(m, __shfl_xor_sync(0xffffffffu, m, o));
    if (lane == 0) red[wid] = m;
    __syncthreads();
    m = red[0];
#pragma unroll
    for (int w = 1; w < 8; w++) m = fmaxf(m, red[w]);
    __syncthreads();

    float s = 0.0f;
#pragma unroll
    for (int i = 0; i < 8; i++) {
        v[i] = expf(v[i] - m);
        s += v[i];
    }
#pragma unroll
    for (int o = 16; o > 0; o >>= 1) s += __shfl_xor_sync(0xffffffffu, s, o);
    if (lane == 0) red[wid] = s;
    __syncthreads();
    s = red[0];
#pragma unroll
    for (int w = 1; w < 8; w++) s += red[w];
    const float inv = 1.0f / s;
#pragma unroll
    for (int i = 0; i < 8; i++)
        orow[tid + i * 256] = __float2half_rn(v[i] * inv);
}

// ---------------- launch ----------------
extern "C" void kernel_launch(void* const* d_in, const int* in_sizes, int n_in,
                              void* d_out, int out_size) {
    const float* x  = (const float*)d_in[0];
    const float* Wq = (const float*)d_in[1];
    const float* bq = (const float*)d_in[2];
    const float* Wk = (const float*)d_in[3];
    const float* bk = (const float*)d_in[4];
    const float* Wv = (const float*)d_in[5];
    const float* bv = (const float*)d_in[6];
    float* out = (float*)d_out;

    __half *xh, *wh, *wl, *qkvh, *qkvl, *ph;
    float* p;
    cudaGetSymbolAddress((void**)&xh, gx_hi);
    cudaGetSymbolAddress((void**)&wh, gw_hi);
    cudaGetSymbolAddress((void**)&wl, gw_lo);
    cudaGetSymbolAddress((void**)&qkvh, gqkv_hi);
    cudaGetSymbolAddress((void**)&qkvl, gqkv_lo);
    cudaGetSymbolAddress((void**)&p, g_P);
    cudaGetSymbolAddress((void**)&ph, g_Ph);

    cudaFuncSetAttribute(hgemm<0, true>,
                         cudaFuncAttributeMaxDynamicSharedMemorySize, GEMM_SMEM);
    cudaFuncSetAttribute(hgemm<0, false>,
                         cudaFuncAttributeMaxDynamicSharedMemorySize, GEMM_SMEM);
    cudaFuncSetAttribute(hgemm<1, false>,
                         cudaFuncAttributeMaxDynamicSharedMemorySize, GEMM_SMEM);

    // 1) x -> fp16 hi only; W -> hi/lo split
    split_kernel<<<(int)(BSD / 4 / 256), 256>>>(x, xh, nullptr, (int)(BSD / 4));
    const int wn4 = DD * DD / 4;
    split_kernel<<<wn4 / 256, 256>>>(Wq, wh + 0ull * DD * DD, wl + 0ull * DD * DD, wn4);
    split_kernel<<<wn4 / 256, 256>>>(Wk, wh + 1ull * DD * DD, wl + 1ull * DD * DD, wn4);
    split_kernel<<<wn4 / 256, 256>>>(Wv, wh + 2ull * DD * DD, wl + 2ull * DD * DD, wn4);

    // 2) QKV: C[16384,1024] = x_hi @ (W_hi + W_lo) + bias  (B=[K,N] trans path)
    hgemm<0, true><<<dim3(DD / BN, (BB * SS) / BM, 3), NTH, GEMM_SMEM>>>(
        xh, wh, wl, nullptr, qkvh, qkvl, DD, DD,
        0LL, (long long)DD * DD, (long long)BSD, 1.0f, bq, bk, bv);

    // 3) scores: P[b] = Q_hi[b] @ (K_hi + K_lo)[b]^T / 32  (B=K natural [N,K])
    hgemm<1, false><<<dim3(SS / BN, SS / BM, BB), NTH, GEMM_SMEM>>>(
        qkvh, qkvh + BSD, qkvl + BSD, p, nullptr, nullptr, SS, DD,
        (long long)SS * DD, (long long)SS * DD, (long long)SS * SS,
        0.03125f, nullptr, nullptr, nullptr);

    // 4) softmax (fp32 in, fp16-hi out)
    softmax_kernel<<<BB * SS, 256>>>();

    // 5) out[b] = P_hi[b] @ (V_hi + V_lo)[b]  (B=V natural [K,N] trans path)
    hgemm<0, false><<<dim3(DD / BN, SS / BM, BB), NTH, GEMM_SMEM>>>(
        ph, qkvh + 2 * BSD, qkvl + 2 * BSD, out, nullptr, nullptr,
        DD, SS, (long long)SS * SS, (long long)SS * DD, (long long)SS * DD,
        1.0f, nullptr, nullptr, nullptr);
}